// round 1
// baseline (speedup 1.0000x reference)
#include <cuda_runtime.h>
#include <math.h>

#define S     8192
#define SMASK 8191
#define W     64
#define MODES 256
#define NB    64
#define RTOT  4096      // NB*W
#define NM2   512       // 2*MODES

// ---------------- scratch (device globals; no allocations) ----------------
__device__ float d_X0[RTOT * S];          // 128 MB activation ping
__device__ float d_X1[RTOT * S];          // 128 MB activation pong
__device__ float d_CT[NM2 * RTOT];        // forward DFT output, k-major [c][r]
__device__ float d_OT[NM2 * RTOT];        // mode-mixed output,   k-major [c][r]
__device__ float d_Bf[S * NM2];           // forward basis  [n][c]
__device__ float d_Bi[NM2 * S];           // inverse basis  [c][n] (scales folded)
__device__ float d_WTr[4 * MODES * W * W]; // spectral weights re, [l][k][i][o]
__device__ float d_WTi[4 * MODES * W * W]; // spectral weights im

__device__ __forceinline__ float gelu_f(float x) {
    return 0.5f * x * (1.0f + erff(x * 0.7071067811865476f));
}

// ---------------- basis generation (exact power-of-two phase reduction) ----
__global__ void gen_bf() {
    int idx = blockIdx.x * 256 + threadIdx.x;   // n*256 + k
    int n = idx >> 8, k = idx & 255;
    float ang = (float)((k * n) & SMASK) * (6.283185307179586f / 8192.0f);
    float s, c; sincosf(ang, &s, &c);
    d_Bf[n * NM2 + k]         = c;
    d_Bf[n * NM2 + MODES + k] = -s;
}
__global__ void gen_bi() {
    int idx = blockIdx.x * 256 + threadIdx.x;   // k*8192 + n
    int k = idx >> 13, n = idx & SMASK;
    float ang = (float)((k * n) & SMASK) * (6.283185307179586f / 8192.0f);
    float s, c; sincosf(ang, &s, &c);
    float sc = (k == 0) ? (1.0f / 8192.0f) : (2.0f / 8192.0f);
    d_Bi[k * S + n]           = sc * c;
    d_Bi[(MODES + k) * S + n] = (k == 0) ? 0.0f : -(2.0f / 8192.0f) * s;
}

// ---------------- spectral-weight transpose: [l,i,o,k] -> [l,k,i,o] --------
__global__ void wtrans(const float* __restrict__ swr, const float* __restrict__ swi) {
    __shared__ float t[32][33];
    const float* src = blockIdx.z ? swi : swr;
    float*       dst = blockIdx.z ? d_WTi : d_WTr;
    int k0 = blockIdx.x * 32, R0 = blockIdx.y * 32;   // R = (l*64+i)*64+o
    t[threadIdx.y][threadIdx.x] = src[(R0 + threadIdx.y) * 256 + k0 + threadIdx.x];
    __syncthreads();
    int l = R0 >> 12, io0 = R0 & 4095;
    dst[(l * 256 + k0 + threadIdx.y) * 4096 + io0 + threadIdx.x] = t[threadIdx.x][threadIdx.y];
}

// ---------------- lifting: x = [u, grid] @ fc0_w + fc0_b, channel-major ----
__global__ void lift(const float* __restrict__ u, const float* __restrict__ fc0w,
                     const float* __restrict__ fc0b, float* __restrict__ X) {
    int idx = blockIdx.x * 256 + threadIdx.x;   // (b*64+w)*8192 + s
    int s = idx & SMASK;
    int r = idx >> 13;
    int w = r & 63;
    int b = r >> 6;
    float g = (float)s * (1.0f / 8191.0f);
    X[idx] = u[b * S + s] * fc0w[w] + g * fc0w[64 + w] + fc0b[w];
}

// ---------------- forward DFT GEMM: CT[c][r] = (X @ Bf)^T --------------------
// X [4096 x 8192] row-major, Bf [8192 x 512] row-major. 128x128x16 tile.
__global__ __launch_bounds__(256) void sgemm_fwd(const float* __restrict__ A) {
    __shared__ float As[16][128];
    __shared__ float Bs[16][128];
    int bn = blockIdx.x, bm = blockIdx.y;
    int tid = threadIdx.x;
    int tm = tid >> 4, tn = tid & 15;
    const float* Aptr = A + (size_t)(bm * 128) * S;
    const float* Bptr = d_Bf + bn * 128;
    float acc[8][8];
    #pragma unroll
    for (int i = 0; i < 8; i++)
        #pragma unroll
        for (int j = 0; j < 8; j++) acc[i][j] = 0.0f;

    for (int k0 = 0; k0 < S; k0 += 16) {
        #pragma unroll
        for (int j = 0; j < 2; j++) {
            int idx = tid * 2 + j;                  // 0..511
            int r = idx >> 2, c4 = idx & 3;         // A: 128 rows x 4 float4
            float4 v = *(const float4*)(Aptr + r * S + k0 + c4 * 4);
            As[c4 * 4 + 0][r] = v.x; As[c4 * 4 + 1][r] = v.y;
            As[c4 * 4 + 2][r] = v.z; As[c4 * 4 + 3][r] = v.w;
            int kr = idx >> 5, n4 = idx & 31;       // B: 16 rows x 32 float4
            *(float4*)&Bs[kr][n4 * 4] = *(const float4*)(Bptr + (k0 + kr) * NM2 + n4 * 4);
        }
        __syncthreads();
        #pragma unroll
        for (int kk = 0; kk < 16; kk++) {
            float4 a0 = *(const float4*)&As[kk][tm * 8];
            float4 a1 = *(const float4*)&As[kk][tm * 8 + 4];
            float4 b0 = *(const float4*)&Bs[kk][tn * 8];
            float4 b1 = *(const float4*)&Bs[kk][tn * 8 + 4];
            float av[8] = {a0.x, a0.y, a0.z, a0.w, a1.x, a1.y, a1.z, a1.w};
            float bv[8] = {b0.x, b0.y, b0.z, b0.w, b1.x, b1.y, b1.z, b1.w};
            #pragma unroll
            for (int i = 0; i < 8; i++)
                #pragma unroll
                for (int j = 0; j < 8; j++) acc[i][j] += av[i] * bv[j];
        }
        __syncthreads();
    }
    // transposed store: CT[c][m]
    int m0 = bm * 128 + tm * 8;
    int c0 = bn * 128 + tn * 8;
    #pragma unroll
    for (int j = 0; j < 8; j++) {
        float4 v0 = make_float4(acc[0][j], acc[1][j], acc[2][j], acc[3][j]);
        float4 v1 = make_float4(acc[4][j], acc[5][j], acc[6][j], acc[7][j]);
        *(float4*)&d_CT[(c0 + j) * RTOT + m0]     = v0;
        *(float4*)&d_CT[(c0 + j) * RTOT + m0 + 4] = v1;
    }
}

// ---------------- per-mode complex channel mix -----------------------------
// For mode k: O[b,o] = sum_i Xf[b,i] * Wl[i,o]  (complex). One CTA per k.
__global__ __launch_bounds__(256) void mixk(int l) {
    extern __shared__ float sm[];
    float* Wr = sm;        float* Wi = sm + 4096;
    float* Xr = sm + 8192; float* Xi = sm + 12288;
    int k = blockIdx.x, tid = threadIdx.x;
    const float* wr = d_WTr + (l * MODES + k) * 4096;
    const float* wi = d_WTi + (l * MODES + k) * 4096;
    const float* cr = d_CT + (size_t)k * RTOT;
    const float* ci = d_CT + (size_t)(MODES + k) * RTOT;
    #pragma unroll
    for (int j = 0; j < 16; j++) {
        int idx = tid + 256 * j;
        Wr[idx] = wr[idx]; Wi[idx] = wi[idx];
        Xr[idx] = cr[idx]; Xi[idx] = ci[idx];
    }
    __syncthreads();
    int o = tid & 63;
    int b0 = tid >> 6;               // 0..3 ; thread handles b = b0 + 4*j
    float ar[16], ai[16];
    #pragma unroll
    for (int j = 0; j < 16; j++) { ar[j] = 0.0f; ai[j] = 0.0f; }
    for (int i = 0; i < 64; i++) {
        float wre = Wr[i * 64 + o], wim = Wi[i * 64 + o];
        #pragma unroll
        for (int j = 0; j < 16; j++) {
            int b = b0 + 4 * j;
            float xr = Xr[b * 64 + i], xi = Xi[b * 64 + i];
            ar[j] += xr * wre - xi * wim;
            ai[j] += xr * wim + xi * wre;
        }
    }
    #pragma unroll
    for (int j = 0; j < 16; j++) {
        int lin = tid + 256 * j;
        d_OT[(size_t)k * RTOT + lin]           = ar[j];
        d_OT[(size_t)(MODES + k) * RTOT + lin] = ai[j];
    }
}

// ---------------- fused inverse DFT + pointwise + bias + gelu --------------
// Per batch b: Y[64 x 8192] = [O2 | pw] (64x576) @ [Bi ; Xin_b] (576x8192)
__global__ __launch_bounds__(128) void sgemm_inv(const float* __restrict__ Xin,
                                                 float* __restrict__ Xout,
                                                 const float* __restrict__ pw,
                                                 const float* __restrict__ pwb,
                                                 int dogelu) {
    __shared__ float As[16][64];
    __shared__ float Bs[16][128];
    int b = blockIdx.y;
    int n0 = blockIdx.x * 128;
    int tid = threadIdx.x;
    int tm = tid >> 4, tn = tid & 15;      // tm 0..7 (o), tn 0..15 (n)
    float acc[8][8];
    #pragma unroll
    for (int i = 0; i < 8; i++)
        #pragma unroll
        for (int j = 0; j < 8; j++) acc[i][j] = 0.0f;

    for (int c0 = 0; c0 < 576; c0 += 16) {
        if (c0 < 512) {
            #pragma unroll
            for (int j = 0; j < 2; j++) {
                int idx = tid * 2 + j;              // 0..255 : 16k x 16 float4
                int k = idx >> 4, o4 = idx & 15;
                *(float4*)&As[k][o4 * 4] =
                    *(const float4*)(d_OT + (size_t)(c0 + k) * RTOT + b * 64 + o4 * 4);
            }
            #pragma unroll
            for (int j = 0; j < 4; j++) {
                int idx = tid * 4 + j;              // 0..511 : 16k x 32 float4
                int k = idx >> 5, n4 = idx & 31;
                *(float4*)&Bs[k][n4 * 4] =
                    *(const float4*)(d_Bi + (size_t)(c0 + k) * S + n0 + n4 * 4);
            }
        } else {
            int cc = c0 - 512;
            #pragma unroll
            for (int j = 0; j < 8; j++) {
                int idx = tid * 8 + j;              // 0..1023 scalar
                int o = idx >> 4, k = idx & 15;
                As[k][o] = pw[o * 64 + cc + k];
            }
            #pragma unroll
            for (int j = 0; j < 4; j++) {
                int idx = tid * 4 + j;
                int k = idx >> 5, n4 = idx & 31;
                *(float4*)&Bs[k][n4 * 4] =
                    *(const float4*)(Xin + (size_t)(b * 64 + cc + k) * S + n0 + n4 * 4);
            }
        }
        __syncthreads();
        #pragma unroll
        for (int kk = 0; kk < 16; kk++) {
            float4 a0 = *(const float4*)&As[kk][tm * 8];
            float4 a1 = *(const float4*)&As[kk][tm * 8 + 4];
            float4 b0 = *(const float4*)&Bs[kk][tn * 8];
            float4 b1 = *(const float4*)&Bs[kk][tn * 8 + 4];
            float av[8] = {a0.x, a0.y, a0.z, a0.w, a1.x, a1.y, a1.z, a1.w};
            float bv[8] = {b0.x, b0.y, b0.z, b0.w, b1.x, b1.y, b1.z, b1.w};
            #pragma unroll
            for (int i = 0; i < 8; i++)
                #pragma unroll
                for (int j = 0; j < 8; j++) acc[i][j] += av[i] * bv[j];
        }
        __syncthreads();
    }
    int nbase = n0 + tn * 8;
    #pragma unroll
    for (int i = 0; i < 8; i++) {
        int o = tm * 8 + i;
        float bias = pwb[o];
        float v[8];
        #pragma unroll
        for (int j = 0; j < 8; j++) {
            float t = acc[i][j] + bias;
            v[j] = dogelu ? gelu_f(t) : t;
        }
        *(float4*)&Xout[(size_t)(b * 64 + o) * S + nbase]     = make_float4(v[0], v[1], v[2], v[3]);
        *(float4*)&Xout[(size_t)(b * 64 + o) * S + nbase + 4] = make_float4(v[4], v[5], v[6], v[7]);
    }
}

// ---------------- head: gelu(x^T @ fc1 + b1) @ fc2 + b2 --------------------
__global__ __launch_bounds__(256) void headk(const float* __restrict__ X,
                                             const float* __restrict__ fc1w,
                                             const float* __restrict__ fc1b,
                                             const float* __restrict__ fc2w,
                                             const float* __restrict__ fc2b,
                                             float* __restrict__ out) {
    extern __shared__ float sm[];
    float* fc1s = sm;            // [64][128]
    float* xs   = sm + 8192;     // [64][128], reused for reduction
    float* b1s  = sm + 16384;    // [128]
    float* fc2s = sm + 16512;    // [128]
    int b = blockIdx.y;
    int s0 = blockIdx.x * 128;
    int tid = threadIdx.x;
    #pragma unroll
    for (int j = 0; j < 32; j++) {
        int idx = tid + 256 * j;
        fc1s[idx] = fc1w[idx];
        xs[idx]   = X[(size_t)(b * 64 + (idx >> 7)) * S + s0 + (idx & 127)];
    }
    if (tid < 128) { b1s[tid] = fc1b[tid]; fc2s[tid] = fc2w[tid]; }
    __syncthreads();

    int tm = tid >> 4, tn = tid & 15;   // pt block tm*8, hidden block tn*8
    float acc[8][8];
    #pragma unroll
    for (int i = 0; i < 8; i++)
        #pragma unroll
        for (int j = 0; j < 8; j++) acc[i][j] = 0.0f;
    for (int i = 0; i < 64; i++) {
        float av[8], bv[8];
        #pragma unroll
        for (int ii = 0; ii < 8; ii++) av[ii] = xs[i * 128 + tm * 8 + ii];
        #pragma unroll
        for (int jj = 0; jj < 8; jj++) bv[jj] = fc1s[i * 128 + tn * 8 + jj];
        #pragma unroll
        for (int ii = 0; ii < 8; ii++)
            #pragma unroll
            for (int jj = 0; jj < 8; jj++) acc[ii][jj] += av[ii] * bv[jj];
    }
    float part[8];
    #pragma unroll
    for (int ii = 0; ii < 8; ii++) {
        float p = 0.0f;
        #pragma unroll
        for (int jj = 0; jj < 8; jj++) {
            float h = gelu_f(acc[ii][jj] + b1s[tn * 8 + jj]);
            p += h * fc2s[tn * 8 + jj];
        }
        part[ii] = p;
    }
    __syncthreads();                    // done reading xs -> reuse as reduction buf
    float* red = xs;
    #pragma unroll
    for (int ii = 0; ii < 8; ii++) red[(tm * 8 + ii) * 16 + tn] = part[ii];
    __syncthreads();
    if (tid < 128) {
        float ssum = fc2b[0];
        #pragma unroll
        for (int t = 0; t < 16; t++) ssum += red[tid * 16 + t];
        out[(size_t)b * S + s0 + tid] = ssum;
    }
}

// ---------------------------------------------------------------------------
extern "C" void kernel_launch(void* const* d_in, const int* in_sizes, int n_in,
                              void* d_out, int out_size) {
    const float* u    = (const float*)d_in[0];
    const float* fc0w = (const float*)d_in[1];
    const float* fc0b = (const float*)d_in[2];
    const float* swr  = (const float*)d_in[3];
    const float* swi  = (const float*)d_in[4];
    const float* pww  = (const float*)d_in[5];
    const float* pwb  = (const float*)d_in[6];
    const float* fc1w = (const float*)d_in[7];
    const float* fc1b = (const float*)d_in[8];
    const float* fc2w = (const float*)d_in[9];
    const float* fc2b = (const float*)d_in[10];
    float* out = (float*)d_out;

    cudaFuncSetAttribute(mixk,  cudaFuncAttributeMaxDynamicSharedMemorySize, 65536);
    cudaFuncSetAttribute(headk, cudaFuncAttributeMaxDynamicSharedMemorySize, 66560);

    float *pX0 = nullptr, *pX1 = nullptr;
    cudaGetSymbolAddress((void**)&pX0, d_X0);
    cudaGetSymbolAddress((void**)&pX1, d_X1);

    gen_bf<<<8192, 256>>>();
    gen_bi<<<8192, 256>>>();
    wtrans<<<dim3(8, 512, 2), dim3(32, 32)>>>(swr, swi);
    lift<<<131072, 256>>>(u, fc0w, fc0b, pX0);

    float* Xin = pX0;
    float* Xout = pX1;
    for (int l = 0; l < 4; l++) {
        sgemm_fwd<<<dim3(4, 32), 256>>>(Xin);
        mixk<<<256, 256, 65536>>>(l);
        sgemm_inv<<<dim3(64, 64), 128>>>(Xin, Xout, pww + l * W * W, pwb + l * W,
                                         (l < 3) ? 1 : 0);
        float* t = Xin; Xin = Xout; Xout = t;
    }
    headk<<<dim3(64, 64), 256, 66560>>>(Xin, fc1w, fc1b, fc2w, fc2b, out);
}